// round 1
// baseline (speedup 1.0000x reference)
#include <cuda_runtime.h>

// R-MAC over x[32, 2048, 32, 32] -> out[32, 2048].
// 19 static regions (H=W=32): 1x full, 6x 21x21 (rows {0,5,11} x cols {0,11}),
// 12x 16x16 (rows {0,5,10,16} x cols {0,8,16}).
// Only 6 distinct column segments:
//   seg0=[0,32) seg1=[0,21) seg2=[11,32) seg3=[0,16) seg4=[8,24) seg5=[16,32)

#define WARPS_PER_BLOCK 8
#define NTILES (32 * 2048)

__constant__ int c_reg_i[19]   = {0,  0, 0, 5, 5, 11, 11,  0, 0, 0, 5, 5, 5, 10, 10, 10, 16, 16, 16};
__constant__ int c_reg_rh[19]  = {32, 21,21,21,21,21,21,   16,16,16,16,16,16,16,16,16,16,16,16};
__constant__ int c_reg_seg[19] = {0,  1, 2, 1, 2, 1, 2,    3, 4, 5, 3, 4, 5, 3, 4, 5, 3, 4, 5};

__global__ __launch_bounds__(32 * WARPS_PER_BLOCK)
void rmac_kernel(const float* __restrict__ x, float* __restrict__ out) {
    // Per-warp scratch: 32x32 tile padded to row stride 33 (conflict-free row
    // reads), plus 32x6 segment maxes padded to stride 7 (conflict-free).
    __shared__ float tile[WARPS_PER_BLOCK][32 * 33];
    __shared__ float segm[WARPS_PER_BLOCK][32 * 7];

    const int wib  = threadIdx.x >> 5;
    const int lane = threadIdx.x & 31;
    const int t    = blockIdx.x * WARPS_PER_BLOCK + wib;   // tile = b*C + c

    // ---- Stage tile to smem: 8 fully-coalesced float4 loads per lane ----
    const float4* __restrict__ src =
        reinterpret_cast<const float4*>(x + (size_t)t * 1024);
    float* tl = tile[wib];
#pragma unroll
    for (int k = 0; k < 8; k++) {
        float4 v = src[k * 32 + lane];
        int e   = (k * 32 + lane) << 2;   // element index 0..1023
        int row = e >> 5;
        int col = e & 31;                  // multiple of 4, same row for all 4
        float* d = tl + row * 33 + col;    // STS banks: (row + col) distinct per lane
        d[0] = v.x; d[1] = v.y; d[2] = v.z; d[3] = v.w;
    }
    __syncwarp();

    // ---- Per-row (lane = row) segment maxes ----
    const float* r = tl + lane * 33;       // bank (lane + c) % 32: conflict-free
    float g[8];
#pragma unroll
    for (int k = 0; k < 8; k++) {
        float a = fmaxf(r[4 * k],     r[4 * k + 1]);
        float b = fmaxf(r[4 * k + 2], r[4 * k + 3]);
        g[k] = fmaxf(a, b);                // max over cols [4k, 4k+4)
    }
    float r11 = r[11], r20 = r[20];
    float s3 = fmaxf(fmaxf(g[0], g[1]), fmaxf(g[2], g[3]));  // [0,16)
    float s4 = fmaxf(fmaxf(g[2], g[3]), fmaxf(g[4], g[5]));  // [8,24)
    float s5 = fmaxf(fmaxf(g[4], g[5]), fmaxf(g[6], g[7]));  // [16,32)
    float s0 = fmaxf(s3, s5);                                // [0,32)
    float s1 = fmaxf(s3, fmaxf(g[4], r20));                  // [0,21) = [0,16)+[16,20)+{20}
    float s2 = fmaxf(r11, fmaxf(g[3], s5));                  // [11,32) = {11}+[12,16)+[16,32)

    float* sd = segm[wib] + lane * 7;      // stride 7: gcd(7,32)=1, conflict-free
    sd[0] = s0; sd[1] = s1; sd[2] = s2; sd[3] = s3; sd[4] = s4; sd[5] = s5;
    __syncwarp();

    // ---- Lanes 0..18: one region each = max over its row range ----
    float acc = 0.0f;
    if (lane < 19) {
        const int i0 = c_reg_i[lane];
        const int rh = c_reg_rh[lane];
        const float* sp = segm[wib] + c_reg_seg[lane];
        float m = sp[i0 * 7];
        for (int q = 1; q < rh; q++) m = fmaxf(m, sp[(i0 + q) * 7]);
        acc = m;
    }

    // ---- Sum the 19 region maxes across the warp ----
#pragma unroll
    for (int off = 16; off; off >>= 1)
        acc += __shfl_xor_sync(0xffffffffu, acc, off);
    if (lane == 0) out[t] = acc;
}

extern "C" void kernel_launch(void* const* d_in, const int* in_sizes, int n_in,
                              void* d_out, int out_size) {
    const float* x = (const float*)d_in[0];
    float* out = (float*)d_out;
    (void)in_sizes; (void)n_in; (void)out_size;
    rmac_kernel<<<NTILES / WARPS_PER_BLOCK, 32 * WARPS_PER_BLOCK>>>(x, out);
}

// round 2
// speedup vs baseline: 1.0378x; 1.0378x over previous
#include <cuda_runtime.h>

// R-MAC over x[32, 2048, 32, 32] -> out[32, 2048].
// 19 static regions (H=W=32): 1x full (32x32), 6x 21x21 (rows {0,5,11} x cols
// {0,11}), 12x 16x16 (rows {0,5,10,16} x cols {0,8,16}).
// Column segments: s1=[0,21) s2=[11,32) s3=[0,16) s4=[8,24) s5=[16,32), s0=[0,32).
// All region row-ranges decompose into boundary-aligned row blocks:
//   segs 1,2 (fam B): blocks [0,5)[5,11)[11,16)[16,21)[21,26)[26,32)
//   segs 3,4,5 (fam C): blocks [0,5)[5,10)[10,16)[16,21)[21,26)[26,32)

#define WPB 8
#define NTILES (32 * 2048)

__constant__ int c_start[2][6] = {{0, 5, 11, 16, 21, 26}, {0, 5, 10, 16, 21, 26}};
__constant__ int c_sz6[2][6]   = {{0, 1, 0, 0, 0, 1},     {0, 0, 1, 0, 0, 1}};  // 1 if block has 6 rows
// region -> (base index into bmbuf, count). bmbuf idx = (seg-1)*6 + block.
// regions 1-6: 21x21, 4 blocks each; regions 7-18: 16x16, 3 blocks each.
__constant__ int c_rbase[19] = {0, 0, 6, 1, 7, 2, 8,
                                12, 18, 24, 13, 19, 25, 14, 20, 26, 15, 21, 27};
__constant__ int c_rcnt4[19] = {0, 1, 1, 1, 1, 1, 1, 0, 0, 0, 0, 0, 0, 0, 0, 0, 0, 0, 0};

__global__ __launch_bounds__(32 * WPB)
void rmac_kernel(const float* __restrict__ x, float* __restrict__ out) {
    // Per-warp scratch. gbuf: 32 rows x 8 col-group maxes, stride 9 (read
    // conflict-free; write has only 3 banks 2-way). rbuf: col-11 / col-20 values.
    __shared__ float gbuf[WPB][32 * 9];
    __shared__ float rbuf[WPB][64];
    __shared__ float segm[WPB][32 * 7];
    __shared__ float bmbuf[WPB][32];

    const int wib  = threadIdx.x >> 5;
    const int lane = threadIdx.x & 31;
    const int t    = blockIdx.x * WPB + wib;       // tile = b*C + c

    const float4* __restrict__ src =
        reinterpret_cast<const float4*>(x + (size_t)t * 1024);
    const int a = lane >> 3;                        // row sub-index within k-step
    const int cg = lane & 7;                        // column group (4 cols)

    // ---- Stage 1: coalesced streaming loads, reduce 4->1 in regs, tiny STS ----
    float4 v[8];
#pragma unroll
    for (int k = 0; k < 8; k++) v[k] = __ldcs(src + k * 32 + lane);

    float* g = gbuf[wib];
#pragma unroll
    for (int k = 0; k < 8; k++) {
        const int row = 4 * k + a;
        float m = fmaxf(fmaxf(v[k].x, v[k].y), fmaxf(v[k].z, v[k].w));
        g[row * 9 + cg] = m;
        if (cg == 2) rbuf[wib][row] = v[k].w;       // col 11
        if (cg == 5) rbuf[wib][32 + row] = v[k].x;  // col 20
    }
    __syncwarp();

    // ---- Stage 2: lane = row; build 6 column-segment maxes ----
    float gg[8];
#pragma unroll
    for (int c = 0; c < 8; c++) gg[c] = g[lane * 9 + c];   // banks 9*lane+c: conflict-free
    const float r11 = rbuf[wib][lane];
    const float r20 = rbuf[wib][32 + lane];

    const float s3 = fmaxf(fmaxf(gg[0], gg[1]), fmaxf(gg[2], gg[3]));  // [0,16)
    const float s4 = fmaxf(fmaxf(gg[2], gg[3]), fmaxf(gg[4], gg[5]));  // [8,24)
    const float s5 = fmaxf(fmaxf(gg[4], gg[5]), fmaxf(gg[6], gg[7]));  // [16,32)
    const float s0 = fmaxf(s3, s5);                                    // [0,32)
    const float s1 = fmaxf(s3, fmaxf(gg[4], r20));                     // [0,21)
    const float s2 = fmaxf(r11, fmaxf(gg[3], s5));                     // [11,32)

    // Full-image region: max over rows of s0 via shuffle butterfly (no smem).
    float full = s0;
#pragma unroll
    for (int off = 16; off; off >>= 1)
        full = fmaxf(full, __shfl_xor_sync(0xffffffffu, full, off));

    float* sd = segm[wib] + lane * 7;               // stride 7: conflict-free
    sd[1] = s1; sd[2] = s2; sd[3] = s3; sd[4] = s4; sd[5] = s5;
    __syncwarp();

    // ---- Stage 3a: 30 (segment, row-block) maxes, <=6 LDS each ----
    if (lane < 30) {
        const int s   = 1 + lane / 6;               // segment 1..5
        const int blk = lane % 6;
        const int fam = (s >= 3);
        const int st  = c_start[fam][blk];
        const float* sp = segm[wib] + s;
        float bm = sp[st * 7];
#pragma unroll
        for (int q = 1; q < 5; q++) bm = fmaxf(bm, sp[(st + q) * 7]);
        if (c_sz6[fam][blk]) bm = fmaxf(bm, sp[(st + 5) * 7]);
        bmbuf[wib][lane] = bm;
    }
    __syncwarp();

    // ---- Stage 3b: 19 region maxes (lane 0 = full image), then warp sum ----
    float acc = 0.0f;
    if (lane == 0) {
        acc = full;
    } else if (lane < 19) {
        const float* bp = bmbuf[wib];
        const int base = c_rbase[lane];
        float m = fmaxf(bp[base], bp[base + 1]);
        m = fmaxf(m, bp[base + 2]);
        if (c_rcnt4[lane]) m = fmaxf(m, bp[base + 3]);
        acc = m;
    }
#pragma unroll
    for (int off = 16; off; off >>= 1)
        acc += __shfl_xor_sync(0xffffffffu, acc, off);
    if (lane == 0) out[t] = acc;
}

extern "C" void kernel_launch(void* const* d_in, const int* in_sizes, int n_in,
                              void* d_out, int out_size) {
    const float* x = (const float*)d_in[0];
    float* out = (float*)d_out;
    (void)in_sizes; (void)n_in; (void)out_size;
    rmac_kernel<<<NTILES / WPB, 32 * WPB>>>(x, out);
}